// round 2
// baseline (speedup 1.0000x reference)
#include <cuda_runtime.h>

typedef unsigned long long ull;

#define NTOK 16384
#define DDIM 2048
#define NEXP 64
#define TMB  32                 // tokens per block
#define KB   64                 // k-tile
#define KITER (DDIM / KB)       // 32
#define NBLK (NTOK / TMB)       // 512

__device__ float g_wt[DDIM * NEXP];       // W^T [k][e], 512 KB
__device__ float g_logits[NTOK * NEXP];   // raw x.W^T, 4 MB

__device__ __forceinline__ ull pack2(float lo, float hi) {
    ull r; asm("mov.b64 %0, {%1,%2};" : "=l"(r) : "f"(lo), "f"(hi)); return r;
}
__device__ __forceinline__ ull ffma2(ull a, ull b, ull c) {
    ull d; asm("fma.rn.f32x2 %0, %1, %2, %3;" : "=l"(d) : "l"(a), "l"(b), "l"(c)); return d;
}

// ---------------- W transpose: W[e][k] -> g_wt[k][e] ----------------
__global__ __launch_bounds__(256) void wt_kernel(const float* __restrict__ W) {
    int i = blockIdx.x * 256 + threadIdx.x;   // 131072 total
    int k = i >> 6, e = i & 63;
    g_wt[i] = W[e * DDIM + k];
}

// ---------------- GEMM: 32 tokens x 64 experts per block ----------------
__global__ __launch_bounds__(128) void gemm_kernel(const float* __restrict__ x) {
    __shared__ float xs[KB * TMB];    // [k][tok]  8 KB
    __shared__ float ws[KB * NEXP];   // [k][e]   16 KB

    const int t    = threadIdx.x;
    const int tg   = t & 15;          // token pair: tokens 2tg, 2tg+1
    const int eg   = t >> 4;          // expert group: experts eg*8 .. eg*8+7
    const int ltok = t & 31;          // x loader: token row
    const int lkq  = t >> 5;          // x loader: k quarter (16 k each)

    const float* xg = x + (long)blockIdx.x * TMB * DDIM + ltok * DDIM + lkq * 16;

    ull acc[2][4];
#pragma unroll
    for (int i = 0; i < 2; ++i)
#pragma unroll
        for (int j = 0; j < 4; ++j) acc[i][j] = 0ULL;

    float4 xr[4], wr[8];
    // prefetch tile 0
    {
#pragma unroll
        for (int q = 0; q < 4; ++q) xr[q] = *(const float4*)(xg + q * 4);
        const float4* w4 = (const float4*)g_wt;
#pragma unroll
        for (int i = 0; i < 8; ++i) wr[i] = w4[t + i * 128];
    }

    for (int it = 0; it < KITER; ++it) {
        __syncthreads();   // prior compute done before overwrite
        // stage x transposed: xs[k][tok]  (STS conflict-free: addr = k*32 + lane)
#pragma unroll
        for (int q = 0; q < 4; ++q) {
            int kl = lkq * 16 + q * 4;
            xs[(kl + 0) * TMB + ltok] = xr[q].x;
            xs[(kl + 1) * TMB + ltok] = xr[q].y;
            xs[(kl + 2) * TMB + ltok] = xr[q].z;
            xs[(kl + 3) * TMB + ltok] = xr[q].w;
        }
        // stage W^T tile: straight float4 copy, conflict-free
        {
            float4* wsm4 = (float4*)ws;
#pragma unroll
            for (int i = 0; i < 8; ++i) wsm4[t + i * 128] = wr[i];
        }
        __syncthreads();

        // prefetch next tile (overlaps compute)
        if (it + 1 < KITER) {
            const float* xb = xg + (it + 1) * KB;
#pragma unroll
            for (int q = 0; q < 4; ++q) xr[q] = *(const float4*)(xb + q * 4);
            const float4* w4 = (const float4*)(g_wt + (it + 1) * KB * NEXP);
#pragma unroll
            for (int i = 0; i < 8; ++i) wr[i] = w4[t + i * 128];
        }

#pragma unroll 16
        for (int kk = 0; kk < KB; ++kk) {
            float2 xv = *(const float2*)&xs[kk * TMB + 2 * tg];      // LDS.64, 1 wf/warp
            ull x0 = pack2(xv.x, xv.x);
            ull x1 = pack2(xv.y, xv.y);
            ulonglong2 wv0 = *(const ulonglong2*)&ws[kk * NEXP + eg * 8];     // LDS.128 bcast
            ulonglong2 wv1 = *(const ulonglong2*)&ws[kk * NEXP + eg * 8 + 4]; // LDS.128 bcast
            acc[0][0] = ffma2(x0, wv0.x, acc[0][0]);
            acc[0][1] = ffma2(x0, wv0.y, acc[0][1]);
            acc[0][2] = ffma2(x0, wv1.x, acc[0][2]);
            acc[0][3] = ffma2(x0, wv1.y, acc[0][3]);
            acc[1][0] = ffma2(x1, wv0.x, acc[1][0]);
            acc[1][1] = ffma2(x1, wv0.y, acc[1][1]);
            acc[1][2] = ffma2(x1, wv1.x, acc[1][2]);
            acc[1][3] = ffma2(x1, wv1.y, acc[1][3]);
        }
    }

    // store raw logits: 2 x STG.128 per token, consecutive experts
    const long tokbase = (long)blockIdx.x * TMB + 2 * tg;
#pragma unroll
    for (int i = 0; i < 2; ++i) {
        ulonglong2 a, b;
        a.x = acc[i][0]; a.y = acc[i][1];
        b.x = acc[i][2]; b.y = acc[i][3];
        *(ulonglong2*)&g_logits[(tokbase + i) * NEXP + eg * 8]     = a;
        *(ulonglong2*)&g_logits[(tokbase + i) * NEXP + eg * 8 + 4] = b;
    }
}

// ---------------- epilogue: softmax + top2 + scatter ----------------
__global__ __launch_bounds__(256) void epi_kernel(
    const float* __restrict__ sc,
    const float* __restrict__ noise,
    const int*   __restrict__ sidx_p,
    float*       __restrict__ out,
    int do_probs, int do_idx)
{
    const long tk = (long)blockIdx.x * 256 + threadIdx.x;
    const float f = 1.0f + 0.1f * sc[sidx_p[0]];

    const float4* lg = (const float4*)(g_logits + tk * NEXP);
    const float4* nz = (const float4*)(noise + tk * NEXP);

    float lr[NEXP];
    float m = -1e30f;
#pragma unroll
    for (int q = 0; q < 16; ++q) {
        float4 lv = lg[q];
        float4 nv = nz[q];
        float v0 = fmaf(f, lv.x, 0.1f * nv.x);
        float v1 = fmaf(f, lv.y, 0.1f * nv.y);
        float v2 = fmaf(f, lv.z, 0.1f * nv.z);
        float v3 = fmaf(f, lv.w, 0.1f * nv.w);
        lr[q * 4 + 0] = v0; lr[q * 4 + 1] = v1;
        lr[q * 4 + 2] = v2; lr[q * 4 + 3] = v3;
        m = fmaxf(m, fmaxf(fmaxf(v0, v1), fmaxf(v2, v3)));
    }

    // top-2 on raw logits: exact ordering, lowest index wins ties (strict >)
    float b1 = -1e30f, b2 = -1e30f;
    int   i1 = 0,      i2 = 0;
#pragma unroll
    for (int e = 0; e < NEXP; ++e) {
        float v = lr[e];
        if (v > b1)      { b2 = b1; i2 = i1; b1 = v; i1 = e; }
        else if (v > b2) { b2 = v;  i2 = e; }
    }

    float sum = 0.0f;
#pragma unroll
    for (int e = 0; e < NEXP; ++e) {
        float p = __expf(lr[e] - m);
        lr[e] = p;
        sum += p;
    }
    const float inv = 1.0f / sum;
    const float p1  = __expf(b1 - m);
    const float p2  = __expf(b2 - m);
    const float wn  = 1.0f / (p1 + p2);
    const float w1v = p1 * wn, w2v = p2 * wn;

    // dense dispatch tensor
    float4* disp = (float4*)out + tk * 16;
#pragma unroll
    for (int q = 0; q < 16; ++q) {
        float4 z = make_float4(0.f, 0.f, 0.f, 0.f);
        if ((i1 >> 2) == q) (&z.x)[i1 & 3] = w1v;
        if ((i2 >> 2) == q) (&z.x)[i2 & 3] = w2v;
        disp[q] = z;
    }
    if (do_probs) {
        float4* pr = (float4*)(out + (long)NTOK * NEXP) + tk * 16;
#pragma unroll
        for (int q = 0; q < 16; ++q) {
            float4 z;
            z.x = lr[q * 4 + 0] * inv;
            z.y = lr[q * 4 + 1] * inv;
            z.z = lr[q * 4 + 2] * inv;
            z.w = lr[q * 4 + 3] * inv;
            pr[q] = z;
        }
    }
    if (do_idx) {
        float* ix = out + 2L * NTOK * NEXP + tk * 2;
        ix[0] = (float)i1;
        ix[1] = (float)i2;
    }
}

extern "C" void kernel_launch(void* const* d_in, const int* in_sizes, int n_in,
                              void* d_out, int out_size) {
    const float* x     = (const float*)d_in[0];
    const float* W     = (const float*)d_in[1];
    const float* sc    = (const float*)d_in[2];
    const float* noise = (const float*)d_in[3];
    const int*   sidx  = (const int*)d_in[4];
    float* out = (float*)d_out;

    const int do_probs = (out_size >= 2 * NTOK * NEXP) ? 1 : 0;
    const int do_idx   = (out_size >= 2 * NTOK * NEXP + 2 * NTOK) ? 1 : 0;

    wt_kernel<<<(DDIM * NEXP) / 256, 256>>>(W);
    gemm_kernel<<<NBLK, 128>>>(x);
    epi_kernel<<<NTOK / 256, 256>>>(sc, noise, sidx, out, do_probs, do_idx);
}

// round 4
// speedup vs baseline: 2.0354x; 2.0354x over previous
#include <cuda_runtime.h>
#include <cuda_bf16.h>

typedef unsigned int u32;

#define NTOK 16384
#define DDIM 2048
#define NEXP 64
#define TMB  128
#define KC   64
#define NCHUNK (DDIM/KC)     // 32
#define NBLK (NTOK/TMB)      // 128
#define LSTR 66

#define XHI 0
#define XLO 16384
#define WHI 32768
#define WLO 40960
#define SMEM_BYTES 49152

static __device__ __forceinline__ u32 smem_u32(const void* p) {
    u32 a; asm("{ .reg .u64 t; cvta.to.shared.u64 t, %1; cvt.u32.u64 %0, t; }" : "=r"(a) : "l"(p));
    return a;
}
// pack (v0 -> low half, v1 -> high half)
static __device__ __forceinline__ u32 pack_bf16(float v0, float v1) {
    u32 r; asm("cvt.rn.bf16x2.f32 %0, %1, %2;" : "=r"(r) : "f"(v1), "f"(v0)); return r;
}

#define LDM_X4(r0,r1,r2,r3, addr) \
    asm volatile("ldmatrix.sync.aligned.m8n8.x4.shared.b16 {%0,%1,%2,%3}, [%4];" \
        : "=r"(r0),"=r"(r1),"=r"(r2),"=r"(r3) : "r"(addr))

#define MMA16816(d, a, b0, b1) \
    asm volatile("mma.sync.aligned.m16n8k16.row.col.f32.bf16.bf16.f32 " \
        "{%0,%1,%2,%3}, {%4,%5,%6,%7}, {%8,%9}, {%0,%1,%2,%3};" \
        : "+f"((d)[0]),"+f"((d)[1]),"+f"((d)[2]),"+f"((d)[3]) \
        : "r"((a)[0]),"r"((a)[1]),"r"((a)[2]),"r"((a)[3]),"r"(b0),"r"(b1))

__global__ __launch_bounds__(256, 1) void moe_main(
    const float* __restrict__ x,
    const float* __restrict__ W,
    const float* __restrict__ sc,
    const float* __restrict__ noise,
    const int*   __restrict__ sidx_p,
    float*       __restrict__ out,
    int do_probs, int do_idx)
{
    extern __shared__ __align__(16) char dsm[];
    const u32 sb = smem_u32(dsm);

    const int t   = threadIdx.x;
    const int wid = t >> 5;
    const int lid = t & 31;

    // warp tile: m0 in {0,32,64,96}, n0 in {0,32}
    const int m0 = (wid >> 1) * 32;
    const int n0 = (wid & 1) * 32;
    // ldmatrix lane decomposition
    const int tokA = lid & 15;            // A: row within m16 tile
    const int kqA  = lid >> 4;            // A: k 16-byte half
    const int eB   = (lid & 7) + ((lid >> 4) << 3);   // B: expert row
    const int kqB  = (lid >> 3) & 1;                  // B: k half

    // x loader: token = t>>1, k-half (t&1)*32 of each 64-k chunk
    const int xrow = t >> 1;
    const float* xg = x + (long)blockIdx.x * TMB * DDIM + (long)xrow * DDIM + (t & 1) * 32;
    const u32 xsb = (u32)xrow * 128u + (u32)(t & 1) * 64u;   // byte base in x tile

    // W loader: slots t and t+256; slot s -> e = s>>3, kq = s&7 (8 k per slot)
    const int we0 = t >> 3,        wkq = t & 7;
    const int we1 = (t >> 3) + 32;
    const float* wg0 = W + (long)we0 * DDIM + wkq * 8;
    const float* wg1 = W + (long)we1 * DDIM + wkq * 8;

    float acc[2][4][4];
#pragma unroll
    for (int i = 0; i < 2; ++i)
#pragma unroll
        for (int j = 0; j < 4; ++j)
#pragma unroll
            for (int r = 0; r < 4; ++r) acc[i][j][r] = 0.0f;

    float4 xr[8], wr[4];
    // prefetch chunk 0
#pragma unroll
    for (int q = 0; q < 8; ++q) xr[q] = *(const float4*)(xg + q * 4);
    wr[0] = *(const float4*)(wg0);
    wr[1] = *(const float4*)(wg0 + 4);
    wr[2] = *(const float4*)(wg1);
    wr[3] = *(const float4*)(wg1 + 4);

#pragma unroll 1
    for (int it = 0; it < NCHUNK; ++it) {
        __syncthreads();   // prior chunk's smem reads complete

        // ---- convert + store x hi/lo (SW128-swizzled) ----
#pragma unroll
        for (int qq = 0; qq < 4; ++qq) {
            float4 a = xr[2 * qq], b = xr[2 * qq + 1];
            u32 h01 = pack_bf16(a.x, a.y);
            u32 h23 = pack_bf16(a.z, a.w);
            u32 h45 = pack_bf16(b.x, b.y);
            u32 h67 = pack_bf16(b.z, b.w);
            float f0 = __uint_as_float(h01 << 16), f1 = __uint_as_float(h01 & 0xffff0000u);
            float f2 = __uint_as_float(h23 << 16), f3 = __uint_as_float(h23 & 0xffff0000u);
            float f4 = __uint_as_float(h45 << 16), f5 = __uint_as_float(h45 & 0xffff0000u);
            float f6 = __uint_as_float(h67 << 16), f7 = __uint_as_float(h67 & 0xffff0000u);
            u32 l01 = pack_bf16(a.x - f0, a.y - f1);
            u32 l23 = pack_bf16(a.z - f2, a.w - f3);
            u32 l45 = pack_bf16(b.x - f4, b.y - f5);
            u32 l67 = pack_bf16(b.z - f6, b.w - f7);
            u32 o = xsb + (u32)qq * 16u;
            u32 sw = o ^ (((u32)xrow & 7u) << 4);
            *(uint4*)(dsm + XHI + sw) = make_uint4(h01, h23, h45, h67);
            *(uint4*)(dsm + XLO + sw) = make_uint4(l01, l23, l45, l67);
        }
        // ---- convert + store W hi/lo ----
#pragma unroll
        for (int s = 0; s < 2; ++s) {
            float4 a = wr[2 * s], b = wr[2 * s + 1];
            int e = s ? we1 : we0;
            u32 h01 = pack_bf16(a.x, a.y);
            u32 h23 = pack_bf16(a.z, a.w);
            u32 h45 = pack_bf16(b.x, b.y);
            u32 h67 = pack_bf16(b.z, b.w);
            float f0 = __uint_as_float(h01 << 16), f1 = __uint_as_float(h01 & 0xffff0000u);
            float f2 = __uint_as_float(h23 << 16), f3 = __uint_as_float(h23 & 0xffff0000u);
            float f4 = __uint_as_float(h45 << 16), f5 = __uint_as_float(h45 & 0xffff0000u);
            float f6 = __uint_as_float(h67 << 16), f7 = __uint_as_float(h67 & 0xffff0000u);
            u32 l01 = pack_bf16(a.x - f0, a.y - f1);
            u32 l23 = pack_bf16(a.z - f2, a.w - f3);
            u32 l45 = pack_bf16(b.x - f4, b.y - f5);
            u32 l67 = pack_bf16(b.z - f6, b.w - f7);
            u32 o = (u32)e * 128u + (u32)wkq * 16u;
            u32 sw = o ^ (((u32)e & 7u) << 4);
            *(uint4*)(dsm + WHI + sw) = make_uint4(h01, h23, h45, h67);
            *(uint4*)(dsm + WLO + sw) = make_uint4(l01, l23, l45, l67);
        }
        __syncthreads();

        // ---- prefetch next chunk (overlaps compute) ----
        if (it + 1 < NCHUNK) {
            const float* xb = xg + (it + 1) * KC;
#pragma unroll
            for (int q = 0; q < 8; ++q) xr[q] = *(const float4*)(xb + q * 4);
            const int ko = (it + 1) * KC;
            wr[0] = *(const float4*)(wg0 + ko);
            wr[1] = *(const float4*)(wg0 + ko + 4);
            wr[2] = *(const float4*)(wg1 + ko);
            wr[3] = *(const float4*)(wg1 + ko + 4);
        }

        // ---- tensor-core compute: 4 k16 steps ----
#pragma unroll
        for (int kk = 0; kk < 4; ++kk) {
            u32 ah[2][4], al[2][4], bh[8], bl[8];
#pragma unroll
            for (int mt = 0; mt < 2; ++mt) {
                int tok = m0 + mt * 16 + tokA;
                u32 sw = (u32)(((kk * 2 + kqA) ^ (tokA & 7)) << 4);
                u32 aaddr = sb + XHI + (u32)tok * 128u + sw;
                LDM_X4(ah[mt][0], ah[mt][1], ah[mt][2], ah[mt][3], aaddr);
                LDM_X4(al[mt][0], al[mt][1], al[mt][2], al[mt][3], aaddr + (XLO - XHI));
            }
#pragma unroll
            for (int ng = 0; ng < 2; ++ng) {
                int ef = n0 + ng * 16 + eB;
                u32 sw = (u32)(((kk * 2 + kqB) ^ (eB & 7)) << 4);
                u32 baddr = sb + WHI + (u32)ef * 128u + sw;
                LDM_X4(bh[ng*4+0], bh[ng*4+1], bh[ng*4+2], bh[ng*4+3], baddr);
                LDM_X4(bl[ng*4+0], bl[ng*4+1], bl[ng*4+2], bl[ng*4+3], baddr + (WLO - WHI));
            }
#pragma unroll
            for (int mt = 0; mt < 2; ++mt) {
#pragma unroll
                for (int j = 0; j < 4; ++j) {
                    int bi = (j >> 1) * 4 + (j & 1) * 2;
                    MMA16816(acc[mt][j], ah[mt], bh[bi], bh[bi + 1]);   // hi*hi
                    MMA16816(acc[mt][j], ah[mt], bl[bi], bl[bi + 1]);   // hi*lo
                    MMA16816(acc[mt][j], al[mt], bh[bi], bh[bi + 1]);   // lo*hi
                }
            }
        }
    }

    __syncthreads();
    // ---- spill accumulators to smem logits [tok][e], stride LSTR ----
    {
        float* lg = (float*)dsm;
        const int r  = lid >> 2;
        const int c2 = (lid & 3) * 2;
#pragma unroll
        for (int mt = 0; mt < 2; ++mt) {
#pragma unroll
            for (int j = 0; j < 4; ++j) {
                int tok = m0 + mt * 16 + r;
                int e   = n0 + j * 8 + c2;
                lg[tok * LSTR + e]           = acc[mt][j][0];
                lg[tok * LSTR + e + 1]       = acc[mt][j][1];
                lg[(tok + 8) * LSTR + e]     = acc[mt][j][2];
                lg[(tok + 8) * LSTR + e + 1] = acc[mt][j][3];
            }
        }
    }
    __syncthreads();

    // ---- epilogue: one token per thread (t < 128) ----
    if (t < TMB) {
        const long tokg = (long)blockIdx.x * TMB + t;
        const float f = 1.0f + 0.1f * sc[sidx_p[0]];
        float* lrow = (float*)dsm + t * LSTR;
        const float4* nz = (const float4*)(noise + tokg * NEXP);

        float lr[NEXP];
        float m = -1e30f;
#pragma unroll
        for (int q = 0; q < 16; ++q) {
            float4 nv = nz[q];
            float v0 = fmaf(f, lrow[q * 4 + 0], 0.1f * nv.x);
            float v1 = fmaf(f, lrow[q * 4 + 1], 0.1f * nv.y);
            float v2 = fmaf(f, lrow[q * 4 + 2], 0.1f * nv.z);
            float v3 = fmaf(f, lrow[q * 4 + 3], 0.1f * nv.w);
            lr[q * 4 + 0] = v0; lr[q * 4 + 1] = v1;
            lr[q * 4 + 2] = v2; lr[q * 4 + 3] = v3;
            m = fmaxf(m, fmaxf(fmaxf(v0, v1), fmaxf(v2, v3)));
        }

        // top-2 on raw logits (strict >: lowest index wins ties, matches lax.top_k)
        float b1 = -1e30f, b2 = -1e30f;
        int   i1 = 0,      i2 = 0;
#pragma unroll
        for (int e = 0; e < NEXP; ++e) {
            float v = lr[e];
            if (v > b1)      { b2 = b1; i2 = i1; b1 = v; i1 = e; }
            else if (v > b2) { b2 = v;  i2 = e; }
        }

        float sum = 0.0f;
#pragma unroll
        for (int e = 0; e < NEXP; ++e) {
            float pb = __expf(lr[e] - m);
            lr[e] = pb;
            sum += pb;
        }
        const float inv = 1.0f / sum;
        const float p1  = __expf(b1 - m);
        const float p2  = __expf(b2 - m);
        const float wn  = 1.0f / (p1 + p2);
        const float w1v = p1 * wn, w2v = p2 * wn;

        float4* disp = (float4*)out + tokg * 16;
#pragma unroll
        for (int q = 0; q < 16; ++q) {
            float4 z = make_float4(0.f, 0.f, 0.f, 0.f);
            if ((i1 >> 2) == q) (&z.x)[i1 & 3] = w1v;
            if ((i2 >> 2) == q) (&z.x)[i2 & 3] = w2v;
            disp[q] = z;
        }
        if (do_probs) {
            float4* pr = (float4*)(out + (long)NTOK * NEXP) + tokg * 16;
#pragma unroll
            for (int q = 0; q < 16; ++q) {
                float4 z;
                z.x = lr[q * 4 + 0] * inv;
                z.y = lr[q * 4 + 1] * inv;
                z.z = lr[q * 4 + 2] * inv;
                z.w = lr[q * 4 + 3] * inv;
                pr[q] = z;
            }
        }
        if (do_idx) {
            float* ix = out + 2L * NTOK * NEXP + tokg * 2;
            ix[0] = (float)i1;
            ix[1] = (float)i2;
        }
    }
}

extern "C" void kernel_launch(void* const* d_in, const int* in_sizes, int n_in,
                              void* d_out, int out_size) {
    const float* x     = (const float*)d_in[0];
    const float* W     = (const float*)d_in[1];
    const float* sc    = (const float*)d_in[2];
    const float* noise = (const float*)d_in[3];
    const int*   sidx  = (const int*)d_in[4];
    float* out = (float*)d_out;

    const int do_probs = (out_size >= 2 * NTOK * NEXP) ? 1 : 0;
    const int do_idx   = (out_size >= 2 * NTOK * NEXP + 2 * NTOK) ? 1 : 0;

    static int configured = 0;
    cudaFuncSetAttribute(moe_main, cudaFuncAttributeMaxDynamicSharedMemorySize, SMEM_BYTES);
    (void)configured;

    moe_main<<<NBLK, 256, SMEM_BYTES>>>(x, W, sc, noise, sidx, out, do_probs, do_idx);
}

// round 5
// speedup vs baseline: 2.1247x; 1.0439x over previous
#include <cuda_runtime.h>
#include <cuda_bf16.h>

typedef unsigned int u32;

#define NTOK 16384
#define DDIM 2048
#define NEXP 64
#define TMB  128
#define KC   64
#define NCHUNK (DDIM/KC)     // 32
#define NBLK (NTOK/TMB)      // 128
#define LSTR 66

// double-buffered smem layout (bytes)
#define XHI(p) ((p) * 16384)
#define XLO(p) (32768 + (p) * 16384)
#define WHI(p) (65536 + (p) * 8192)
#define WLO(p) (81920 + (p) * 8192)
#define SMEM_BYTES 98304

static __device__ __forceinline__ u32 smem_u32(const void* p) {
    u32 a; asm("{ .reg .u64 t; cvta.to.shared.u64 t, %1; cvt.u32.u64 %0, t; }" : "=r"(a) : "l"(p));
    return a;
}
// pack (v0 -> low half, v1 -> high half)
static __device__ __forceinline__ u32 pack_bf16(float v0, float v1) {
    u32 r; asm("cvt.rn.bf16x2.f32 %0, %1, %2;" : "=r"(r) : "f"(v1), "f"(v0)); return r;
}

#define LDM_X4(r0,r1,r2,r3, addr) \
    asm volatile("ldmatrix.sync.aligned.m8n8.x4.shared.b16 {%0,%1,%2,%3}, [%4];" \
        : "=r"(r0),"=r"(r1),"=r"(r2),"=r"(r3) : "r"(addr))

#define MMA16816(d, a, b0, b1) \
    asm volatile("mma.sync.aligned.m16n8k16.row.col.f32.bf16.bf16.f32 " \
        "{%0,%1,%2,%3}, {%4,%5,%6,%7}, {%8,%9}, {%0,%1,%2,%3};" \
        : "+f"((d)[0]),"+f"((d)[1]),"+f"((d)[2]),"+f"((d)[3]) \
        : "r"((a)[0]),"r"((a)[1]),"r"((a)[2]),"r"((a)[3]),"r"(b0),"r"(b1))

__global__ __launch_bounds__(256, 1) void moe_main(
    const float* __restrict__ x,
    const float* __restrict__ W,
    const float* __restrict__ sc,
    const float* __restrict__ noise,
    const int*   __restrict__ sidx_p,
    float*       __restrict__ out,
    int do_probs, int do_idx)
{
    extern __shared__ __align__(16) char dsm[];
    const u32 sb = smem_u32(dsm);

    const int t   = threadIdx.x;
    const int wid = t >> 5;
    const int lid = t & 31;

    // warp tile: m0 in {0,32,64,96}, n0 in {0,32}
    const int m0 = (wid >> 1) * 32;
    const int n0 = (wid & 1) * 32;
    const int tokA = lid & 15;
    const int kqA  = lid >> 4;
    const int eB   = (lid & 7) + ((lid >> 4) << 3);
    const int kqB  = (lid >> 3) & 1;

    // x loader: token = t>>1, k-half (t&1)*32 of each 64-k chunk
    const int xrow = t >> 1;
    const float* xg = x + (long)blockIdx.x * TMB * DDIM + (long)xrow * DDIM + (t & 1) * 32;
    const u32 xsb = (u32)xrow * 128u + (u32)(t & 1) * 64u;

    // W loader: experts we0, we1, 8 k each
    const int we0 = t >> 3,        wkq = t & 7;
    const int we1 = (t >> 3) + 32;
    const float* wg0 = W + (long)we0 * DDIM + wkq * 8;
    const float* wg1 = W + (long)we1 * DDIM + wkq * 8;

    float acc[2][4][4];
#pragma unroll
    for (int i = 0; i < 2; ++i)
#pragma unroll
        for (int j = 0; j < 4; ++j)
#pragma unroll
            for (int r = 0; r < 4; ++r) acc[i][j][r] = 0.0f;

    float4 xr[8], wr[4];

    // ---- converter: regs -> buf p ----
    auto store_tiles = [&](int p) {
#pragma unroll
        for (int qq = 0; qq < 4; ++qq) {
            float4 a = xr[2 * qq], b = xr[2 * qq + 1];
            u32 h01 = pack_bf16(a.x, a.y);
            u32 h23 = pack_bf16(a.z, a.w);
            u32 h45 = pack_bf16(b.x, b.y);
            u32 h67 = pack_bf16(b.z, b.w);
            float f0 = __uint_as_float(h01 << 16), f1 = __uint_as_float(h01 & 0xffff0000u);
            float f2 = __uint_as_float(h23 << 16), f3 = __uint_as_float(h23 & 0xffff0000u);
            float f4 = __uint_as_float(h45 << 16), f5 = __uint_as_float(h45 & 0xffff0000u);
            float f6 = __uint_as_float(h67 << 16), f7 = __uint_as_float(h67 & 0xffff0000u);
            u32 l01 = pack_bf16(a.x - f0, a.y - f1);
            u32 l23 = pack_bf16(a.z - f2, a.w - f3);
            u32 l45 = pack_bf16(b.x - f4, b.y - f5);
            u32 l67 = pack_bf16(b.z - f6, b.w - f7);
            u32 o = xsb + (u32)qq * 16u;
            u32 sw = o ^ (((u32)xrow & 7u) << 4);
            *(uint4*)(dsm + XHI(p) + sw) = make_uint4(h01, h23, h45, h67);
            *(uint4*)(dsm + XLO(p) + sw) = make_uint4(l01, l23, l45, l67);
        }
#pragma unroll
        for (int s = 0; s < 2; ++s) {
            float4 a = wr[2 * s], b = wr[2 * s + 1];
            int e = s ? we1 : we0;
            u32 h01 = pack_bf16(a.x, a.y);
            u32 h23 = pack_bf16(a.z, a.w);
            u32 h45 = pack_bf16(b.x, b.y);
            u32 h67 = pack_bf16(b.z, b.w);
            float f0 = __uint_as_float(h01 << 16), f1 = __uint_as_float(h01 & 0xffff0000u);
            float f2 = __uint_as_float(h23 << 16), f3 = __uint_as_float(h23 & 0xffff0000u);
            float f4 = __uint_as_float(h45 << 16), f5 = __uint_as_float(h45 & 0xffff0000u);
            float f6 = __uint_as_float(h67 << 16), f7 = __uint_as_float(h67 & 0xffff0000u);
            u32 l01 = pack_bf16(a.x - f0, a.y - f1);
            u32 l23 = pack_bf16(a.z - f2, a.w - f3);
            u32 l45 = pack_bf16(b.x - f4, b.y - f5);
            u32 l67 = pack_bf16(b.z - f6, b.w - f7);
            u32 o = (u32)e * 128u + (u32)wkq * 16u;
            u32 sw = o ^ (((u32)e & 7u) << 4);
            *(uint4*)(dsm + WHI(p) + sw) = make_uint4(h01, h23, h45, h67);
            *(uint4*)(dsm + WLO(p) + sw) = make_uint4(l01, l23, l45, l67);
        }
    };

    auto load_chunk = [&](int c) {
        const float* xb = xg + c * KC;
#pragma unroll
        for (int q = 0; q < 8; ++q) xr[q] = *(const float4*)(xb + q * 4);
        const int ko = c * KC;
        wr[0] = *(const float4*)(wg0 + ko);
        wr[1] = *(const float4*)(wg0 + ko + 4);
        wr[2] = *(const float4*)(wg1 + ko);
        wr[3] = *(const float4*)(wg1 + ko + 4);
    };

    // prologue: fill buf 0 with chunk 0, prefetch chunk 1
    load_chunk(0);
    store_tiles(0);
    load_chunk(1);
    __syncthreads();

#pragma unroll 1
    for (int it = 0; it < NCHUNK; ++it) {
        const int p = it & 1;

        // 1) stage next chunk into the other buffer (regs hold chunk it+1)
        if (it + 1 < NCHUNK) store_tiles(p ^ 1);
        // 2) issue LDG for chunk it+2 (lands during MMA phase)
        if (it + 2 < NCHUNK) load_chunk(it + 2);

        // 3) tensor-core compute on buffer p
#pragma unroll
        for (int kk = 0; kk < 4; ++kk) {
            u32 ah[2][4], al[2][4], bh[8], bl[8];
#pragma unroll
            for (int mt = 0; mt < 2; ++mt) {
                int tok = m0 + mt * 16 + tokA;
                u32 sw = (u32)(((kk * 2 + kqA) ^ (tokA & 7)) << 4);
                u32 aaddr = sb + XHI(p) + (u32)tok * 128u + sw;
                LDM_X4(ah[mt][0], ah[mt][1], ah[mt][2], ah[mt][3], aaddr);
                LDM_X4(al[mt][0], al[mt][1], al[mt][2], al[mt][3], aaddr + 32768u);
            }
#pragma unroll
            for (int ng = 0; ng < 2; ++ng) {
                int ef = n0 + ng * 16 + eB;
                u32 sw = (u32)(((kk * 2 + kqB) ^ (eB & 7)) << 4);
                u32 baddr = sb + WHI(p) + (u32)ef * 128u + sw;
                LDM_X4(bh[ng*4+0], bh[ng*4+1], bh[ng*4+2], bh[ng*4+3], baddr);
                LDM_X4(bl[ng*4+0], bl[ng*4+1], bl[ng*4+2], bl[ng*4+3], baddr + 16384u);
            }
#pragma unroll
            for (int mt = 0; mt < 2; ++mt) {
#pragma unroll
                for (int j = 0; j < 4; ++j) {
                    int bi = (j >> 1) * 4 + (j & 1) * 2;
                    MMA16816(acc[mt][j], ah[mt], bh[bi], bh[bi + 1]);   // hi*hi
                    MMA16816(acc[mt][j], ah[mt], bl[bi], bl[bi + 1]);   // hi*lo
                    MMA16816(acc[mt][j], al[mt], bh[bi], bh[bi + 1]);   // lo*hi
                }
            }
        }

        // 4) single barrier per chunk
        __syncthreads();
    }

    // ---- spill accumulators to smem logits [tok][e], stride LSTR ----
    {
        float* lg = (float*)dsm;
        const int r  = lid >> 2;
        const int c2 = (lid & 3) * 2;
#pragma unroll
        for (int mt = 0; mt < 2; ++mt) {
#pragma unroll
            for (int j = 0; j < 4; ++j) {
                int tok = m0 + mt * 16 + r;
                int e   = n0 + j * 8 + c2;
                lg[tok * LSTR + e]           = acc[mt][j][0];
                lg[tok * LSTR + e + 1]       = acc[mt][j][1];
                lg[(tok + 8) * LSTR + e]     = acc[mt][j][2];
                lg[(tok + 8) * LSTR + e + 1] = acc[mt][j][3];
            }
        }
    }
    __syncthreads();

    // ---- epilogue: one token per thread (t < 128) ----
    if (t < TMB) {
        const long tokg = (long)blockIdx.x * TMB + t;
        const float f = 1.0f + 0.1f * sc[sidx_p[0]];
        float* lrow = (float*)dsm + t * LSTR;
        const float4* nz = (const float4*)(noise + tokg * NEXP);

        float lr[NEXP];
        float m = -1e30f;
#pragma unroll
        for (int q = 0; q < 16; ++q) {
            float4 nv = nz[q];
            float v0 = fmaf(f, lrow[q * 4 + 0], 0.1f * nv.x);
            float v1 = fmaf(f, lrow[q * 4 + 1], 0.1f * nv.y);
            float v2 = fmaf(f, lrow[q * 4 + 2], 0.1f * nv.z);
            float v3 = fmaf(f, lrow[q * 4 + 3], 0.1f * nv.w);
            lr[q * 4 + 0] = v0; lr[q * 4 + 1] = v1;
            lr[q * 4 + 2] = v2; lr[q * 4 + 3] = v3;
            m = fmaxf(m, fmaxf(fmaxf(v0, v1), fmaxf(v2, v3)));
        }

        // top-2 on raw logits (strict >: lowest index wins ties, matches lax.top_k)
        float b1 = -1e30f, b2 = -1e30f;
        int   i1 = 0,      i2 = 0;
#pragma unroll
        for (int e = 0; e < NEXP; ++e) {
            float v = lr[e];
            if (v > b1)      { b2 = b1; i2 = i1; b1 = v; i1 = e; }
            else if (v > b2) { b2 = v;  i2 = e; }
        }

        float sum = 0.0f;
#pragma unroll
        for (int e = 0; e < NEXP; ++e) {
            float pb = __expf(lr[e] - m);
            lr[e] = pb;
            sum += pb;
        }
        const float inv = 1.0f / sum;
        const float p1  = __expf(b1 - m);
        const float p2  = __expf(b2 - m);
        const float wn  = 1.0f / (p1 + p2);
        const float w1v = p1 * wn, w2v = p2 * wn;

        float4* disp = (float4*)out + tokg * 16;
#pragma unroll
        for (int q = 0; q < 16; ++q) {
            float4 z = make_float4(0.f, 0.f, 0.f, 0.f);
            if ((i1 >> 2) == q) (&z.x)[i1 & 3] = w1v;
            if ((i2 >> 2) == q) (&z.x)[i2 & 3] = w2v;
            disp[q] = z;
        }
        if (do_probs) {
            float4* pr = (float4*)(out + (long)NTOK * NEXP) + tokg * 16;
#pragma unroll
            for (int q = 0; q < 16; ++q) {
                float4 z;
                z.x = lr[q * 4 + 0] * inv;
                z.y = lr[q * 4 + 1] * inv;
                z.z = lr[q * 4 + 2] * inv;
                z.w = lr[q * 4 + 3] * inv;
                pr[q] = z;
            }
        }
        if (do_idx) {
            float* ix = out + 2L * NTOK * NEXP + tokg * 2;
            ix[0] = (float)i1;
            ix[1] = (float)i2;
        }
    }
}

extern "C" void kernel_launch(void* const* d_in, const int* in_sizes, int n_in,
                              void* d_out, int out_size) {
    const float* x     = (const float*)d_in[0];
    const float* W     = (const float*)d_in[1];
    const float* sc    = (const float*)d_in[2];
    const float* noise = (const float*)d_in[3];
    const int*   sidx  = (const int*)d_in[4];
    float* out = (float*)d_out;

    const int do_probs = (out_size >= 2 * NTOK * NEXP) ? 1 : 0;
    const int do_idx   = (out_size >= 2 * NTOK * NEXP + 2 * NTOK) ? 1 : 0;

    cudaFuncSetAttribute(moe_main, cudaFuncAttributeMaxDynamicSharedMemorySize, SMEM_BYTES);
    moe_main<<<NBLK, 256, SMEM_BYTES>>>(x, W, sc, noise, sidx, out, do_probs, do_idx);
}

// round 6
// speedup vs baseline: 2.1362x; 1.0054x over previous
#include <cuda_runtime.h>
#include <cuda_bf16.h>

typedef unsigned int u32;

#define NTOK 16384
#define DDIM 2048
#define NEXP 64
#define TMB  64              // tokens per CTA
#define KC   64
#define NCHUNK (DDIM/KC)     // 32
#define NBLK (NTOK/TMB)      // 256
#define LSTR 66

// double-buffered smem layout (bytes): each tile 64x64 bf16 = 8KB
#define XHI(p) ((p) * 8192)
#define XLO(p) (16384 + (p) * 8192)
#define WHI(p) (32768 + (p) * 8192)
#define WLO(p) (49152 + (p) * 8192)
#define SMEM_BYTES 65536

static __device__ __forceinline__ u32 smem_u32(const void* p) {
    u32 a; asm("{ .reg .u64 t; cvta.to.shared.u64 t, %1; cvt.u32.u64 %0, t; }" : "=r"(a) : "l"(p));
    return a;
}
// pack (v0 -> low half, v1 -> high half)
static __device__ __forceinline__ u32 pack_bf16(float v0, float v1) {
    u32 r; asm("cvt.rn.bf16x2.f32 %0, %1, %2;" : "=r"(r) : "f"(v1), "f"(v0)); return r;
}

#define LDM_X4(r0,r1,r2,r3, addr) \
    asm volatile("ldmatrix.sync.aligned.m8n8.x4.shared.b16 {%0,%1,%2,%3}, [%4];" \
        : "=r"(r0),"=r"(r1),"=r"(r2),"=r"(r3) : "r"(addr))

#define MMA16816(d, a, b0, b1) \
    asm volatile("mma.sync.aligned.m16n8k16.row.col.f32.bf16.bf16.f32 " \
        "{%0,%1,%2,%3}, {%4,%5,%6,%7}, {%8,%9}, {%0,%1,%2,%3};" \
        : "+f"((d)[0]),"+f"((d)[1]),"+f"((d)[2]),"+f"((d)[3]) \
        : "r"((a)[0]),"r"((a)[1]),"r"((a)[2]),"r"((a)[3]),"r"(b0),"r"(b1))

__global__ __launch_bounds__(256, 2) void moe_main(
    const float* __restrict__ x,
    const float* __restrict__ W,
    const float* __restrict__ sc,
    const float* __restrict__ noise,
    const int*   __restrict__ sidx_p,
    float*       __restrict__ out,
    int do_probs, int do_idx)
{
    extern __shared__ __align__(16) char dsm[];
    const u32 sb = smem_u32(dsm);

    const int t   = threadIdx.x;
    const int wid = t >> 5;
    const int lid = t & 31;

    // warp tile: m0 in {0,16,32,48} (m16), n0 in {0,32} (n32)
    const int m0 = (wid >> 1) * 16;
    const int n0 = (wid & 1) * 32;
    const int tokA = lid & 15;
    const int kqA  = lid >> 4;
    const int eB   = (lid & 7) + ((lid >> 4) << 3);
    const int kqB  = (lid >> 3) & 1;

    // loaders: both x (64 tok) and W (64 exp) tiles are 64x64 f32 per chunk;
    // thread covers row = t>>2, k-quarter (t&3)*16 (16 consecutive f32)
    const int lrow = t >> 2;
    const int lq   = t & 3;
    const float* xg = x + (long)blockIdx.x * TMB * DDIM + (long)lrow * DDIM + lq * 16;
    const float* wg = W + (long)lrow * DDIM + lq * 16;
    const u32 tsb = (u32)lrow * 128u + (u32)lq * 32u;   // byte base in bf16 tile
    const u32 swz = ((u32)lrow & 7u) << 4;

    float acc[4][4];
#pragma unroll
    for (int j = 0; j < 4; ++j)
#pragma unroll
        for (int r = 0; r < 4; ++r) acc[j][r] = 0.0f;

    float4 xr[4], wr[4];

    // convert 8 f32 -> hi uint4 + lo uint4
    auto conv8 = [&](float4 a, float4 b, uint4& hi, uint4& lo) {
        u32 h01 = pack_bf16(a.x, a.y);
        u32 h23 = pack_bf16(a.z, a.w);
        u32 h45 = pack_bf16(b.x, b.y);
        u32 h67 = pack_bf16(b.z, b.w);
        float f0 = __uint_as_float(h01 << 16), f1 = __uint_as_float(h01 & 0xffff0000u);
        float f2 = __uint_as_float(h23 << 16), f3 = __uint_as_float(h23 & 0xffff0000u);
        float f4 = __uint_as_float(h45 << 16), f5 = __uint_as_float(h45 & 0xffff0000u);
        float f6 = __uint_as_float(h67 << 16), f7 = __uint_as_float(h67 & 0xffff0000u);
        hi = make_uint4(h01, h23, h45, h67);
        lo = make_uint4(pack_bf16(a.x - f0, a.y - f1),
                        pack_bf16(a.z - f2, a.w - f3),
                        pack_bf16(b.x - f4, b.y - f5),
                        pack_bf16(b.z - f6, b.w - f7));
    };

    auto store_tiles = [&](int p) {
#pragma unroll
        for (int qq = 0; qq < 2; ++qq) {
            uint4 hi, lo;
            u32 sw = (tsb + (u32)qq * 16u) ^ swz;
            conv8(xr[2 * qq], xr[2 * qq + 1], hi, lo);
            *(uint4*)(dsm + XHI(p) + sw) = hi;
            *(uint4*)(dsm + XLO(p) + sw) = lo;
            conv8(wr[2 * qq], wr[2 * qq + 1], hi, lo);
            *(uint4*)(dsm + WHI(p) + sw) = hi;
            *(uint4*)(dsm + WLO(p) + sw) = lo;
        }
    };

    auto load_chunk = [&](int c) {
        const float* xb = xg + c * KC;
        const float* wb = wg + c * KC;
#pragma unroll
        for (int q = 0; q < 4; ++q) xr[q] = *(const float4*)(xb + q * 4);
#pragma unroll
        for (int q = 0; q < 4; ++q) wr[q] = *(const float4*)(wb + q * 4);
    };

    // prologue
    load_chunk(0);
    store_tiles(0);
    load_chunk(1);
    __syncthreads();

#pragma unroll 1
    for (int it = 0; it < NCHUNK; ++it) {
        const int p = it & 1;

        if (it + 1 < NCHUNK) store_tiles(p ^ 1);   // stage chunk it+1
        if (it + 2 < NCHUNK) load_chunk(it + 2);   // LDG chunk it+2 under MMAs

#pragma unroll
        for (int kk = 0; kk < 4; ++kk) {
            u32 ah[4], al[4], bh[8], bl[8];
            {
                int tok = m0 + tokA;
                u32 sw = (u32)(((kk * 2 + kqA) ^ (tokA & 7)) << 4);
                u32 aaddr = sb + XHI(p) + (u32)tok * 128u + sw;
                LDM_X4(ah[0], ah[1], ah[2], ah[3], aaddr);
                LDM_X4(al[0], al[1], al[2], al[3], aaddr + 16384u);
            }
#pragma unroll
            for (int ng = 0; ng < 2; ++ng) {
                int ef = n0 + ng * 16 + eB;
                u32 sw = (u32)(((kk * 2 + kqB) ^ (eB & 7)) << 4);
                u32 baddr = sb + WHI(p) + (u32)ef * 128u + sw;
                LDM_X4(bh[ng*4+0], bh[ng*4+1], bh[ng*4+2], bh[ng*4+3], baddr);
                LDM_X4(bl[ng*4+0], bl[ng*4+1], bl[ng*4+2], bl[ng*4+3], baddr + 16384u);
            }
#pragma unroll
            for (int j = 0; j < 4; ++j) {
                int bi = (j >> 1) * 4 + (j & 1) * 2;
                MMA16816(acc[j], ah, bh[bi], bh[bi + 1]);   // hi*hi
                MMA16816(acc[j], ah, bl[bi], bl[bi + 1]);   // hi*lo
                MMA16816(acc[j], al, bh[bi], bh[bi + 1]);   // lo*hi
            }
        }

        __syncthreads();
    }

    // ---- spill accumulators to smem logits [tok][e], stride LSTR ----
    {
        float* lg = (float*)dsm;
        const int r  = lid >> 2;
        const int c2 = (lid & 3) * 2;
#pragma unroll
        for (int j = 0; j < 4; ++j) {
            int tok = m0 + r;
            int e   = n0 + j * 8 + c2;
            lg[tok * LSTR + e]           = acc[j][0];
            lg[tok * LSTR + e + 1]       = acc[j][1];
            lg[(tok + 8) * LSTR + e]     = acc[j][2];
            lg[(tok + 8) * LSTR + e + 1] = acc[j][3];
        }
    }
    __syncthreads();

    // ---- epilogue: one token per thread (t < 64) ----
    if (t < TMB) {
        const long tokg = (long)blockIdx.x * TMB + t;
        const float f = 1.0f + 0.1f * sc[sidx_p[0]];
        float* lrowp = (float*)dsm + t * LSTR;
        const float4* nz = (const float4*)(noise + tokg * NEXP);

        float lr[NEXP];
        float m = -1e30f;
#pragma unroll
        for (int q = 0; q < 16; ++q) {
            float4 nv = nz[q];
            float v0 = fmaf(f, lrowp[q * 4 + 0], 0.1f * nv.x);
            float v1 = fmaf(f, lrowp[q * 4 + 1], 0.1f * nv.y);
            float v2 = fmaf(f, lrowp[q * 4 + 2], 0.1f * nv.z);
            float v3 = fmaf(f, lrowp[q * 4 + 3], 0.1f * nv.w);
            lr[q * 4 + 0] = v0; lr[q * 4 + 1] = v1;
            lr[q * 4 + 2] = v2; lr[q * 4 + 3] = v3;
            m = fmaxf(m, fmaxf(fmaxf(v0, v1), fmaxf(v2, v3)));
        }

        // top-2 on raw logits (strict >: lowest index wins ties, matches lax.top_k)
        float b1 = -1e30f, b2 = -1e30f;
        int   i1 = 0,      i2 = 0;
#pragma unroll
        for (int e = 0; e < NEXP; ++e) {
            float v = lr[e];
            if (v > b1)      { b2 = b1; i2 = i1; b1 = v; i1 = e; }
            else if (v > b2) { b2 = v;  i2 = e; }
        }

        float sum = 0.0f;
#pragma unroll
        for (int e = 0; e < NEXP; ++e) {
            float pb = __expf(lr[e] - m);
            lr[e] = pb;
            sum += pb;
        }
        const float inv = 1.0f / sum;
        const float p1  = __expf(b1 - m);
        const float p2  = __expf(b2 - m);
        const float wn  = 1.0f / (p1 + p2);
        const float w1v = p1 * wn, w2v = p2 * wn;

        float4* disp = (float4*)out + tokg * 16;
#pragma unroll
        for (int q = 0; q < 16; ++q) {
            float4 z = make_float4(0.f, 0.f, 0.f, 0.f);
            if ((i1 >> 2) == q) (&z.x)[i1 & 3] = w1v;
            if ((i2 >> 2) == q) (&z.x)[i2 & 3] = w2v;
            disp[q] = z;
        }
        if (do_probs) {
            float4* pr = (float4*)(out + (long)NTOK * NEXP) + tokg * 16;
#pragma unroll
            for (int q = 0; q < 16; ++q) {
                float4 z;
                z.x = lr[q * 4 + 0] * inv;
                z.y = lr[q * 4 + 1] * inv;
                z.z = lr[q * 4 + 2] * inv;
                z.w = lr[q * 4 + 3] * inv;
                pr[q] = z;
            }
        }
        if (do_idx) {
            float* ix = out + 2L * NTOK * NEXP + tokg * 2;
            ix[0] = (float)i1;
            ix[1] = (float)i2;
        }
    }
}

extern "C" void kernel_launch(void* const* d_in, const int* in_sizes, int n_in,
                              void* d_out, int out_size) {
    const float* x     = (const float*)d_in[0];
    const float* W     = (const float*)d_in[1];
    const float* sc    = (const float*)d_in[2];
    const float* noise = (const float*)d_in[3];
    const int*   sidx  = (const int*)d_in[4];
    float* out = (float*)d_out;

    const int do_probs = (out_size >= 2 * NTOK * NEXP) ? 1 : 0;
    const int do_idx   = (out_size >= 2 * NTOK * NEXP + 2 * NTOK) ? 1 : 0;

    cudaFuncSetAttribute(moe_main, cudaFuncAttributeMaxDynamicSharedMemorySize, SMEM_BYTES);
    moe_main<<<NBLK, 256, SMEM_BYTES>>>(x, W, sc, noise, sidx, out, do_probs, do_idx);
}